// round 3
// baseline (speedup 1.0000x reference)
#include <cuda_runtime.h>
#include <cstdint>

#define BS  64
#define SEQ 512
#define IN  256
#define HID 512
#define G4  (4*HID)   // 2048

// packed f32x2 FMA: acc.{lo,hi} += a.{lo,hi} * b.{lo,hi}
#define FMA2(acc, a, b) \
    asm("fma.rn.f32x2 %0, %1, %2, %0;" : "+l"(acc) : "l"(a), "l"(b))

// ---------------- device scratch (no allocations allowed) ----------------
__device__ float g_pre[(size_t)SEQ * BS * G4];   // [t][b][col], 268 MB
__device__ float g_whp[(size_t)HID * G4];        // packed Wh: [jc][dj][g][k], 4 MB
__device__ float g_h[2][BS * HID];               // ping-pong hidden state
__device__ float g_c[BS * HID];                  // cell state

// ---------------- activations (MUFU-based, fast-math independent) --------
__device__ __forceinline__ float frcp(float x) {
    float r; asm("rcp.approx.ftz.f32 %0, %1;" : "=f"(r) : "f"(x)); return r;
}
__device__ __forceinline__ float fsig(float x) {
    return frcp(1.0f + __expf(-x));
}
__device__ __forceinline__ float ftanh(float x) {
    // tanh(x) = 2*sigmoid(2x) - 1 ; robust for large |x|
    return fmaf(2.0f, frcp(1.0f + __expf(-2.0f * x)), -1.0f);
}

// ---------------- init: copy h0/c0 into state buffers --------------------
__global__ void init_state(const float* __restrict__ h0, const float* __restrict__ c0) {
    int i = blockIdx.x * 256 + threadIdx.x;   // grid 128 x 256 = 32768
    g_h[0][i] = h0[i];
    g_c[i]    = c0[i];
}

// ---------------- pack Wh: whp[jc][dj][g][k] = Wh[k][g*512 + jc*4 + dj] ---
// Iterate Wh linearly (coalesced reads); scattered 4B writes (~8x amp, one-off).
__global__ void pack_wh(const float* __restrict__ Wh) {
    int idx = blockIdx.x * 256 + threadIdx.x;   // grid 4096 x 256 = 1048576
    int k   = idx >> 11;          // 0..511
    int col = idx & 2047;         // g*512 + jc*4 + dj
    int g   = col >> 9;
    int rem = col & 511;
    int jc  = rem >> 2;
    int dj  = rem & 3;
    g_whp[(((size_t)jc * 4 + dj) * 4 + g) * 512 + k] = Wh[idx];
}

// ---------------- precompute pre[t][b][:] = x[b,t,:] @ Wi + bias ----------
// M = 32768 (r = t*64 + b), N = 2048, K = 256. 64x64 tiles, 4x4 per thread.
__global__ __launch_bounds__(256) void gemm_pre(const float* __restrict__ x,
                                                const float* __restrict__ Wi,
                                                const float* __restrict__ bias) {
    __shared__ float As[16][68];   // [k][m], padded, rows 16B-aligned (272B)
    __shared__ float Bs[16][64];   // [k][n]

    int tid = threadIdx.x;
    int n0 = blockIdx.x * 64;
    int m0 = blockIdx.y * 64;
    int tx = tid & 15, ty = tid >> 4;

    unsigned long long acc01[4], acc23[4];
#pragma unroll
    for (int i = 0; i < 4; i++) { acc01[i] = 0ull; acc23[i] = 0ull; }

    // A-load mapping: one float4 per thread
    int lm = tid >> 2;            // 0..63  (tile row)
    int li = (tid & 3) * 4;       // 0,4,8,12
    int r  = m0 + lm;
    int tt = r >> 6;              // time
    int bb = r & 63;              // batch
    const float* xrow = x + ((size_t)bb * SEQ + tt) * IN;

    // B-load mapping
    int bk = tid >> 4;            // 0..15
    int bn = (tid & 15) * 4;

    for (int k0 = 0; k0 < IN; k0 += 16) {
        float4 xa = *(const float4*)(xrow + k0 + li);
        float4 wb = *(const float4*)(Wi + (size_t)(k0 + bk) * G4 + n0 + bn);
        As[li + 0][lm] = xa.x;
        As[li + 1][lm] = xa.y;
        As[li + 2][lm] = xa.z;
        As[li + 3][lm] = xa.w;
        *(float4*)&Bs[bk][bn] = wb;
        __syncthreads();
#pragma unroll
        for (int k = 0; k < 16; k++) {
            float4 a = *(const float4*)&As[k][ty * 4];
            ulonglong2 bw = *(const ulonglong2*)&Bs[k][tx * 4];
            float av[4] = {a.x, a.y, a.z, a.w};
#pragma unroll
            for (int i = 0; i < 4; i++) {
                unsigned long long aa;
                asm("mov.b64 %0, {%1, %1};" : "=l"(aa) : "r"(__float_as_uint(av[i])));
                FMA2(acc01[i], aa, bw.x);
                FMA2(acc23[i], aa, bw.y);
            }
        }
        __syncthreads();
    }

    float4 bia = *(const float4*)(bias + n0 + tx * 4);
#pragma unroll
    for (int i = 0; i < 4; i++) {
        unsigned p0, p1, p2, p3;
        asm("mov.b64 {%0, %1}, %2;" : "=r"(p0), "=r"(p1) : "l"(acc01[i]));
        asm("mov.b64 {%0, %1}, %2;" : "=r"(p2), "=r"(p3) : "l"(acc23[i]));
        int rr = m0 + ty * 4 + i;
        float4 o;
        o.x = __uint_as_float(p0) + bia.x;
        o.y = __uint_as_float(p1) + bia.y;
        o.z = __uint_as_float(p2) + bia.z;
        o.w = __uint_as_float(p3) + bia.w;
        *(float4*)(g_pre + (size_t)rr * G4 + n0 + tx * 4) = o;
    }
}

// ---------------- one LSTM step ------------------------------------------
// gates = pre[t] + h@Wh ; 4 gate-Lees ; cell update ; c-Lee ; write h,c,out.
// Grid: 128 blocks (jc = 4 hidden cols each), 256 threads: tid = b*4 + dj.
__global__ __launch_bounds__(256) void lstm_step(int t, float* __restrict__ out,
                                                 int write_state) {
    __shared__ float hs[64][132];   // h tile [b][128 k + pad4]; rows 528B (16B-aligned)
    __shared__ float ws[16 * 128];  // Wh tile [dj*4+g][k] for this jc, k-chunk

    int tid = threadIdx.x;
    int b  = tid >> 2;
    int dj = tid & 3;
    int jc = blockIdx.x;

    const float* __restrict__ hprev = g_h[t & 1];
    float* __restrict__ hnext = g_h[(t + 1) & 1];

    // Hoisted loads overlap with the matmul
    size_t prebase = ((size_t)t * BS + b) * G4 + jc * 4 + dj;
    float pre_i = g_pre[prebase + 0 * HID];
    float pre_f = g_pre[prebase + 1 * HID];
    float pre_g = g_pre[prebase + 2 * HID];
    float pre_o = g_pre[prebase + 3 * HID];
    int hidx = b * HID + jc * 4 + dj;
    float c = g_c[hidx];

    unsigned long long a0 = 0ull, a1 = 0ull, a2 = 0ull, a3 = 0ull;
    const float* whbase = g_whp + (size_t)jc * 8192;   // [dj][g][k=512]

    for (int k0 = 0; k0 < HID; k0 += 128) {
        // Wh chunk: 16 rows x 128 floats; fully coalesced 512B row segments
#pragma unroll
        for (int rr = 0; rr < 2; rr++) {
            int grp = rr * 256 + tid;          // 0..511 float4 groups
            int row = grp >> 5;                // 0..15 = dj*4+g
            int kk  = (grp & 31) * 4;
            *(float4*)&ws[row * 128 + kk] = *(const float4*)(whbase + row * 512 + k0 + kk);
        }
        // h chunk: 64 b x 128 k
#pragma unroll
        for (int rr = 0; rr < 8; rr++) {
            int grp = rr * 256 + tid;          // 0..2047 float4 groups
            int hb  = grp >> 5;
            int hk  = (grp & 31) * 4;
            *(float4*)&hs[hb][hk] = *(const float4*)(hprev + hb * HID + k0 + hk);
        }
        __syncthreads();

        const ulonglong2* hp  = (const ulonglong2*)&hs[b][0];
        const ulonglong2* wp0 = (const ulonglong2*)&ws[(dj * 4 + 0) * 128];
        const ulonglong2* wp1 = (const ulonglong2*)&ws[(dj * 4 + 1) * 128];
        const ulonglong2* wp2 = (const ulonglong2*)&ws[(dj * 4 + 2) * 128];
        const ulonglong2* wp3 = (const ulonglong2*)&ws[(dj * 4 + 3) * 128];
#pragma unroll
        for (int k4 = 0; k4 < 32; k4++) {      // 4 k per iter, packed in pairs
            ulonglong2 hh = hp[k4];
            ulonglong2 w0 = wp0[k4];
            ulonglong2 w1 = wp1[k4];
            ulonglong2 w2 = wp2[k4];
            ulonglong2 w3 = wp3[k4];
            FMA2(a0, hh.x, w0.x); FMA2(a0, hh.y, w0.y);
            FMA2(a1, hh.x, w1.x); FMA2(a1, hh.y, w1.y);
            FMA2(a2, hh.x, w2.x); FMA2(a2, hh.y, w2.y);
            FMA2(a3, hh.x, w3.x); FMA2(a3, hh.y, w3.y);
        }
        __syncthreads();
    }

    // horizontal add of packed halves + pre-activation terms
    float xx[4];
    {
        unsigned lo, hi;
        asm("mov.b64 {%0, %1}, %2;" : "=r"(lo), "=r"(hi) : "l"(a0));
        xx[0] = __uint_as_float(lo) + __uint_as_float(hi) + pre_i;
        asm("mov.b64 {%0, %1}, %2;" : "=r"(lo), "=r"(hi) : "l"(a1));
        xx[1] = __uint_as_float(lo) + __uint_as_float(hi) + pre_f;
        asm("mov.b64 {%0, %1}, %2;" : "=r"(lo), "=r"(hi) : "l"(a2));
        xx[2] = __uint_as_float(lo) + __uint_as_float(hi) + pre_g;
        asm("mov.b64 {%0, %1}, %2;" : "=r"(lo), "=r"(hi) : "l"(a3));
        xx[3] = __uint_as_float(lo) + __uint_as_float(hi) + pre_o;
    }

    // ---- 4-wide interleaved Lee oscillators (ILP=4) ----
    float u[4], v[4], z[4], hx[4], dec[4], w0g[4];
#pragma unroll
    for (int l = 0; l < 4; l++) {
        float xv = xx[l];
        w0g[l] = (l == 2) ? ftanh(xv) : fsig(xv);
        dec[l] = __expf(-50.0f * xv * xv);
        hx[l]  = 0.5f * xv;
        u[l] = 0.f; v[l] = 0.f; z[l] = 0.f;
    }
#pragma unroll 1
    for (int it = 0; it < 25; it++) {
#pragma unroll
        for (int l = 0; l < 4; l++) {
            float s  = u[l] + v[l];
            float m  = fmaf(-0.5f, z[l], hx[l]);
            float su = fmaf(0.6f, s, m);
            float sv = fmaf(-0.6f, s, m);
            float u1 = (l == 2) ? ftanh(su) : fsig(su);
            float v1 = (l == 2) ? ftanh(sv) : fsig(sv);
            z[l] = fmaf(u1 - v1, dec[l], w0g[l]);
            u[l] = u1; v[l] = v1;
        }
    }

    // ---- cell update + lee_tanh(c1) ----
    float c1 = fmaf(z[1], c, z[0] * z[2]);     // f*c + i*g

    float wc   = ftanh(c1);
    float decc = __expf(-50.0f * c1 * c1);
    float hxc  = 0.5f * c1;
    float uu = 0.f, vv = 0.f, zz = 0.f;
#pragma unroll 1
    for (int it = 0; it < 25; it++) {
        float s  = uu + vv;
        float m  = fmaf(-0.5f, zz, hxc);
        float u1 = ftanh(fmaf(0.6f, s, m));
        float v1 = ftanh(fmaf(-0.6f, s, m));
        zz = fmaf(u1 - v1, decc, wc);
        uu = u1; vv = v1;
    }

    float h1 = z[3] * zz;                      // o * lee_tanh(c1)
    g_c[hidx]    = c1;
    hnext[hidx]  = h1;
    out[(size_t)b * (SEQ * HID) + (size_t)t * HID + jc * 4 + dj] = h1;

    if (write_state && t == SEQ - 1) {
        out[(size_t)BS * SEQ * HID + hidx]            = h1;   // ht
        out[(size_t)BS * SEQ * HID + BS * HID + hidx] = c1;   // ct
    }
}

// ---------------- launch -------------------------------------------------
extern "C" void kernel_launch(void* const* d_in, const int* in_sizes, int n_in,
                              void* d_out, int out_size) {
    const float* x    = (const float*)d_in[0];
    const float* Wi   = (const float*)d_in[1];
    const float* Wh   = (const float*)d_in[2];
    const float* bias = (const float*)d_in[3];
    const float* h0   = (const float*)d_in[4];
    const float* c0   = (const float*)d_in[5];
    float* out = (float*)d_out;

    init_state<<<128, 256>>>(h0, c0);
    pack_wh<<<4096, 256>>>(Wh);
    dim3 gg(32, 512);
    gemm_pre<<<gg, 256>>>(x, Wi, bias);

    int ws = (out_size >= (int)((size_t)BS * SEQ * HID + 2 * BS * HID)) ? 1 : 0;
    for (int t = 0; t < SEQ; t++) {
        lstm_step<<<128, 256>>>(t, out, ws);
    }
}

// round 9
// speedup vs baseline: 2.9597x; 2.9597x over previous
#include <cuda_runtime.h>
#include <cstdint>

#define BS   64
#define SEQ  512
#define IN   256
#define HID  512
#define G4   2048
#define NCTA 128
#define NTHR 256

// packed f32x2 ops
#define FMA2(acc, a, b) \
    asm("fma.rn.f32x2 %0, %1, %2, %0;" : "+l"(acc) : "l"(a), "l"(b))
#define ADD2(o, a, b) \
    asm("add.rn.f32x2 %0, %1, %2;" : "=l"(o) : "l"(a), "l"(b))

// ---------------- device scratch ----------------
__device__ float g_pre[(size_t)SEQ * BS * G4];   // [t][b][col]
__device__ float g_h[2][HID * BS];               // TRANSPOSED hidden state [k][b]
__device__ unsigned g_bar_cnt;
__device__ unsigned g_bar_gen;

// ---------------- activations (accurate; MUFU EX2+RCP) -------------------
__device__ __forceinline__ float frcp(float x) {
    float r; asm("rcp.approx.ftz.f32 %0, %1;" : "=f"(r) : "f"(x)); return r;
}
__device__ __forceinline__ float fsig(float x) {
    return frcp(1.0f + __expf(-x));
}
__device__ __forceinline__ float ftanh(float x) {
    return fmaf(2.0f, frcp(1.0f + __expf(-2.0f * x)), -1.0f);
}

// ---------------- barrier reset (each launch/replay) ---------------------
__global__ void reset_bar() { g_bar_cnt = 0u; g_bar_gen = 0u; }

// ---------------- grid barrier (all 128 CTAs wave-1 resident) ------------
__device__ __forceinline__ void grid_barrier(unsigned target) {
    __syncthreads();
    if (threadIdx.x == 0) {
        __threadfence();
        unsigned prev = atomicAdd(&g_bar_cnt, 1u);
        if (prev == NCTA - 1u) {
            g_bar_cnt = 0u;
            __threadfence();
            atomicAdd(&g_bar_gen, 1u);
        } else {
            while (*((volatile unsigned*)&g_bar_gen) < target) { }
            __threadfence();
        }
    }
    __syncthreads();
}

// ---------------- precompute pre[t][b][:] = x[b,t,:] @ Wi + bias ----------
__global__ __launch_bounds__(256) void gemm_pre(const float* __restrict__ x,
                                                const float* __restrict__ Wi,
                                                const float* __restrict__ bias) {
    __shared__ float As[16][68];
    __shared__ float Bs[16][64];

    int tid = threadIdx.x;
    int n0 = blockIdx.x * 64;
    int m0 = blockIdx.y * 64;
    int tx = tid & 15, ty = tid >> 4;

    unsigned long long acc01[4], acc23[4];
#pragma unroll
    for (int i = 0; i < 4; i++) { acc01[i] = 0ull; acc23[i] = 0ull; }

    int lm = tid >> 2;
    int li = (tid & 3) * 4;
    int r  = m0 + lm;
    int tt = r >> 6;
    int bb = r & 63;
    const float* xrow = x + ((size_t)bb * SEQ + tt) * IN;

    int bk = tid >> 4;
    int bn = (tid & 15) * 4;

    for (int k0 = 0; k0 < IN; k0 += 16) {
        float4 xa = *(const float4*)(xrow + k0 + li);
        float4 wb = *(const float4*)(Wi + (size_t)(k0 + bk) * G4 + n0 + bn);
        As[li + 0][lm] = xa.x;
        As[li + 1][lm] = xa.y;
        As[li + 2][lm] = xa.z;
        As[li + 3][lm] = xa.w;
        *(float4*)&Bs[bk][bn] = wb;
        __syncthreads();
#pragma unroll
        for (int k = 0; k < 16; k++) {
            float4 a = *(const float4*)&As[k][ty * 4];
            ulonglong2 bw = *(const ulonglong2*)&Bs[k][tx * 4];
            float av[4] = {a.x, a.y, a.z, a.w};
#pragma unroll
            for (int i = 0; i < 4; i++) {
                unsigned long long aa;
                asm("mov.b64 %0, {%1, %1};" : "=l"(aa) : "r"(__float_as_uint(av[i])));
                FMA2(acc01[i], aa, bw.x);
                FMA2(acc23[i], aa, bw.y);
            }
        }
        __syncthreads();
    }

    float4 bia = *(const float4*)(bias + n0 + tx * 4);
#pragma unroll
    for (int i = 0; i < 4; i++) {
        unsigned p0, p1, p2, p3;
        asm("mov.b64 {%0, %1}, %2;" : "=r"(p0), "=r"(p1) : "l"(acc01[i]));
        asm("mov.b64 {%0, %1}, %2;" : "=r"(p2), "=r"(p3) : "l"(acc23[i]));
        int rr = m0 + ty * 4 + i;
        float4 o;
        o.x = __uint_as_float(p0) + bia.x;
        o.y = __uint_as_float(p1) + bia.y;
        o.z = __uint_as_float(p2) + bia.z;
        o.w = __uint_as_float(p3) + bia.w;
        *(float4*)(g_pre + (size_t)rr * G4 + n0 + tx * 4) = o;
    }
}

// ---------------- persistent recurrence kernel ----------------------------
// Grid: 128 CTAs (jc = CTA id, 4 hidden cols), 256 threads.
// Matmul: thread = (col16 = tid&15 -> (g,dj), kq = tid>>4 -> 32-k slice);
//   hs reads are 16-lane broadcasts, ws reads conflict-free.
// Lee:    thread = (lb = tid>>2, lj = tid&3); shared-RCP activation pairs.
// SMEM: ws[512][16] weights (staged once) | hs[512][64] (linear copy) | red[128][66].
__global__ __launch_bounds__(NTHR, 1) void lstm_persist(
    const float* __restrict__ Wh,
    const float* __restrict__ h0,
    const float* __restrict__ c0,
    float* __restrict__ out,
    int write_state) {

    extern __shared__ float smem[];
    float* ws  = smem;                     // 8192 floats
    float* hs  = smem + 8192;              // 32768 floats
    float* red = smem + 8192 + 32768;      // 8448 floats (rows of 66)

    int tid = threadIdx.x;
    int col16 = tid & 15;
    int kq = tid >> 4;                     // 0..15
    int jc = blockIdx.x;
    int lane = tid & 31, wrp = tid >> 5;

    int lb = tid >> 2;                     // Lee: batch
    int lj = tid & 3;                      // Lee: hidden col within jc

    // ---- stage weights once: ws[k*16 + c] = Wh[k][g(c)*512 + jc*4 + dj(c)]
#pragma unroll 4
    for (int it = 0; it < 32; it++) {
        int idx = it * 256 + tid;
        int k = idx >> 4;
        int c = idx & 15;
        ws[idx] = Wh[(size_t)k * G4 + (c >> 2) * HID + jc * 4 + (c & 3)];
    }

    // ---- init transposed state + private cell register
    int hcol = jc * 4 + lj;
    int hidx = lb * HID + hcol;            // row-major index (for out/state)
    int tidx = hcol * BS + lb;             // transposed index
    g_h[0][tidx] = h0[hidx];
    float c_reg = c0[hidx];
    __syncthreads();

    const int kbase = kq * 32;

    for (int t = 0; t < SEQ; t++) {
        // prefetch pre-activation terms (latency hides under barrier wait)
        const float* prerow = g_pre + ((size_t)t * BS + lb) * G4 + hcol;
        float p0 = prerow[0];
        float p1 = prerow[HID];
        float p2 = prerow[2 * HID];
        float p3 = prerow[3 * HID];

        grid_barrier((unsigned)(t + 1));

        // ---- stage h: linear coalesced copy (g_h already [k][b])
        const float* hsrc = g_h[t & 1];
#pragma unroll 8
        for (int it = 0; it < 32; it++) {
            int idx = (it * 256 + tid) * 4;
            *(float4*)&hs[idx] = *(const float4*)(hsrc + idx);
        }
        __syncthreads();

        // ---- matmul: acc over 64 b (32 f32x2 pairs), my col, my k-slice
        unsigned long long acc[32];
#pragma unroll
        for (int i = 0; i < 32; i++) acc[i] = 0ull;

#pragma unroll 4
        for (int kk = 0; kk < 32; kk++) {
            int k = kbase + kk;
            float wv = ws[k * 16 + col16];
            unsigned long long wd;
            asm("mov.b64 %0, {%1, %1};" : "=l"(wd) : "r"(__float_as_uint(wv)));
            const ulonglong2* hp = (const ulonglong2*)&hs[k * 64];
#pragma unroll
            for (int q = 0; q < 16; q++) {
                ulonglong2 hv = hp[q];
                FMA2(acc[2 * q],     hv.x, wd);
                FMA2(acc[2 * q + 1], hv.y, wd);
            }
        }

        // ---- reduce across kq: shfl halves 16-way, smem for the 8 warps
#pragma unroll
        for (int q = 0; q < 32; q++) {
            unsigned long long o = __shfl_xor_sync(0xffffffffu, acc[q], 16);
            unsigned long long s;
            ADD2(s, acc[q], o);
            acc[q] = s;
        }
        if (lane < 16) {
            float* rr = &red[(wrp * 16 + lane) * 66];
#pragma unroll
            for (int q = 0; q < 32; q++)
                *(unsigned long long*)&rr[2 * q] = acc[q];
        }
        __syncthreads();

        // ---- gate sums for (lb, lj)
        float xx[4];
        xx[0] = p0; xx[1] = p1; xx[2] = p2; xx[3] = p3;
#pragma unroll
        for (int gg = 0; gg < 4; gg++) {
            float s = xx[gg];
#pragma unroll
            for (int wv = 0; wv < 8; wv++)
                s += red[(wv * 16 + gg * 4 + lj) * 66 + lb];
            xx[gg] = s;
        }

        // ---- 4-wide interleaved Lee oscillators (i,f,o sig; g tanh)
        // Paired activations share one RCP: u1 = d2*R, v1 = d1*R, R = rcp(d1*d2).
        // hx clamped to +-22 so exp args stay < 88 (no inf -> no NaN via inf*0);
        // exact to tolerance since dec = 0 for |x| >= 44.
        float u[4], v[4], z[4], hx[4], dec[4], w0g[4];
#pragma unroll
        for (int l = 0; l < 4; l++) {
            float xv = xx[l];
            w0g[l] = (l == 2) ? ftanh(xv) : fsig(xv);
            dec[l] = __expf(-50.0f * xv * xv);
            hx[l]  = fminf(fmaxf(0.5f * xv, -22.0f), 22.0f);
            u[l] = 0.f; v[l] = 0.f; z[l] = 0.f;
        }
#pragma unroll 1
        for (int it = 0; it < 25; it++) {
#pragma unroll
            for (int l = 0; l < 4; l++) {
                float s  = u[l] + v[l];
                float m  = fmaf(-0.5f, z[l], hx[l]);
                float su = fmaf(0.6f, s, m);
                float sv = fmaf(-0.6f, s, m);
                float ea, eb;
                if (l == 2) { ea = __expf(-2.0f * su); eb = __expf(-2.0f * sv); }
                else        { ea = __expf(-su);        eb = __expf(-sv); }
                float d1 = 1.0f + ea;
                float d2 = 1.0f + eb;
                float R  = frcp(d1 * d2);
                float u1, v1;
                if (l == 2) {
                    u1 = fmaf(2.0f * d2, R, -1.0f);   // tanh(su)
                    v1 = fmaf(2.0f * d1, R, -1.0f);   // tanh(sv)
                } else {
                    u1 = d2 * R;                       // sig(su)
                    v1 = d1 * R;                       // sig(sv)
                }
                z[l] = fmaf(u1 - v1, dec[l], w0g[l]);
                u[l] = u1; v[l] = v1;
            }
        }

        // ---- cell update + lee_tanh(c1), same shared-RCP pairing
        float c1 = fmaf(z[1], c_reg, z[0] * z[2]);
        float wc   = ftanh(c1);
        float decc = __expf(-50.0f * c1 * c1);
        float hxc  = fminf(fmaxf(0.5f * c1, -22.0f), 22.0f);
        float uu = 0.f, vv = 0.f, zz = 0.f;
#pragma unroll 1
        for (int it = 0; it < 25; it++) {
            float s  = uu + vv;
            float m  = fmaf(-0.5f, zz, hxc);
            float su = fmaf(0.6f, s, m);
            float sv = fmaf(-0.6f, s, m);
            float ea = __expf(-2.0f * su);
            float eb = __expf(-2.0f * sv);
            float d1 = 1.0f + ea;
            float d2 = 1.0f + eb;
            float R  = frcp(d1 * d2);
            float u1 = fmaf(2.0f * d2, R, -1.0f);
            float v1 = fmaf(2.0f * d1, R, -1.0f);
            zz = fmaf(u1 - v1, decc, wc);
            uu = u1; vv = v1;
        }

        float h1 = z[3] * zz;
        c_reg = c1;
        g_h[(t + 1) & 1][tidx] = h1;
        out[(size_t)lb * (SEQ * HID) + (size_t)t * HID + hcol] = h1;

        if (write_state && t == SEQ - 1) {
            out[(size_t)BS * SEQ * HID + hidx]            = h1;
            out[(size_t)BS * SEQ * HID + BS * HID + hidx] = c1;
        }
    }
}

// ---------------- launch -------------------------------------------------
extern "C" void kernel_launch(void* const* d_in, const int* in_sizes, int n_in,
                              void* d_out, int out_size) {
    const float* x    = (const float*)d_in[0];
    const float* Wi   = (const float*)d_in[1];
    const float* Wh   = (const float*)d_in[2];
    const float* bias = (const float*)d_in[3];
    const float* h0   = (const float*)d_in[4];
    const float* c0   = (const float*)d_in[5];
    float* out = (float*)d_out;

    const int SMEM_BYTES = (8192 + 32768 + 8448) * 4;   // 197632 B
    cudaFuncSetAttribute(lstm_persist,
                         cudaFuncAttributeMaxDynamicSharedMemorySize, SMEM_BYTES);

    reset_bar<<<1, 1>>>();
    dim3 gg(32, 512);
    gemm_pre<<<gg, 256>>>(x, Wi, bias);

    int ws = (out_size >= (int)((size_t)BS * SEQ * HID + 2 * BS * HID)) ? 1 : 0;
    lstm_persist<<<NCTA, NTHR, SMEM_BYTES>>>(Wh, h0, c0, out, ws);
}

// round 16
// speedup vs baseline: 2.9781x; 1.0062x over previous
#include <cuda_runtime.h>
#include <cstdint>

#define BS   64
#define SEQ  512
#define IN   256
#define HID  512
#define G4   2048
#define NCTA 128
#define NTHR 256

// packed f32x2 ops
#define FMA2(acc, a, b) \
    asm("fma.rn.f32x2 %0, %1, %2, %0;" : "+l"(acc) : "l"(a), "l"(b))
#define ADD2(o, a, b) \
    asm("add.rn.f32x2 %0, %1, %2;" : "=l"(o) : "l"(a), "l"(b))

// ---------------- device scratch ----------------
__device__ float g_pre[(size_t)SEQ * BS * G4];   // [t][b][col]
__device__ float g_h[2][HID * BS];               // TRANSPOSED hidden state [k][b]
__device__ unsigned g_bar_cnt;
__device__ unsigned g_bar_gen;

// ---------------- activations (accurate; MUFU EX2+RCP) -------------------
__device__ __forceinline__ float frcp(float x) {
    float r; asm("rcp.approx.ftz.f32 %0, %1;" : "=f"(r) : "f"(x)); return r;
}
__device__ __forceinline__ float fsig(float x) {
    return frcp(1.0f + __expf(-x));
}
__device__ __forceinline__ float ftanh(float x) {
    return fmaf(2.0f, frcp(1.0f + __expf(-2.0f * x)), -1.0f);
}

// ---------------- grid barrier (all 128 CTAs wave-1 resident) ------------
__device__ __forceinline__ void grid_barrier(unsigned target) {
    __syncthreads();
    if (threadIdx.x == 0) {
        __threadfence();
        unsigned prev = atomicAdd(&g_bar_cnt, 1u);
        if (prev == NCTA - 1u) {
            g_bar_cnt = 0u;
            __threadfence();
            atomicAdd(&g_bar_gen, 1u);
        } else {
            while (*((volatile unsigned*)&g_bar_gen) < target) { }
            __threadfence();
        }
    }
    __syncthreads();
}

// ---------------- precompute pre[t][b][:] = x[b,t,:] @ Wi + bias ----------
// Also resets the grid-barrier counters (runs before lstm_persist each replay).
__global__ __launch_bounds__(256) void gemm_pre(const float* __restrict__ x,
                                                const float* __restrict__ Wi,
                                                const float* __restrict__ bias) {
    if (blockIdx.x == 0 && blockIdx.y == 0 && threadIdx.x == 0) {
        g_bar_cnt = 0u;
        g_bar_gen = 0u;
    }

    __shared__ float As[16][68];
    __shared__ float Bs[16][64];

    int tid = threadIdx.x;
    int n0 = blockIdx.x * 64;
    int m0 = blockIdx.y * 64;
    int tx = tid & 15, ty = tid >> 4;

    unsigned long long acc01[4], acc23[4];
#pragma unroll
    for (int i = 0; i < 4; i++) { acc01[i] = 0ull; acc23[i] = 0ull; }

    int lm = tid >> 2;
    int li = (tid & 3) * 4;
    int r  = m0 + lm;
    int tt = r >> 6;
    int bb = r & 63;
    const float* xrow = x + ((size_t)bb * SEQ + tt) * IN;

    int bk = tid >> 4;
    int bn = (tid & 15) * 4;

    for (int k0 = 0; k0 < IN; k0 += 16) {
        float4 xa = *(const float4*)(xrow + k0 + li);
        float4 wb = *(const float4*)(Wi + (size_t)(k0 + bk) * G4 + n0 + bn);
        As[li + 0][lm] = xa.x;
        As[li + 1][lm] = xa.y;
        As[li + 2][lm] = xa.z;
        As[li + 3][lm] = xa.w;
        *(float4*)&Bs[bk][bn] = wb;
        __syncthreads();
#pragma unroll
        for (int k = 0; k < 16; k++) {
            float4 a = *(const float4*)&As[k][ty * 4];
            ulonglong2 bw = *(const ulonglong2*)&Bs[k][tx * 4];
            float av[4] = {a.x, a.y, a.z, a.w};
#pragma unroll
            for (int i = 0; i < 4; i++) {
                unsigned long long aa;
                asm("mov.b64 %0, {%1, %1};" : "=l"(aa) : "r"(__float_as_uint(av[i])));
                FMA2(acc01[i], aa, bw.x);
                FMA2(acc23[i], aa, bw.y);
            }
        }
        __syncthreads();
    }

    float4 bia = *(const float4*)(bias + n0 + tx * 4);
#pragma unroll
    for (int i = 0; i < 4; i++) {
        unsigned p0, p1, p2, p3;
        asm("mov.b64 {%0, %1}, %2;" : "=r"(p0), "=r"(p1) : "l"(acc01[i]));
        asm("mov.b64 {%0, %1}, %2;" : "=r"(p2), "=r"(p3) : "l"(acc23[i]));
        int rr = m0 + ty * 4 + i;
        float4 o;
        o.x = __uint_as_float(p0) + bia.x;
        o.y = __uint_as_float(p1) + bia.y;
        o.z = __uint_as_float(p2) + bia.z;
        o.w = __uint_as_float(p3) + bia.w;
        *(float4*)(g_pre + (size_t)rr * G4 + n0 + tx * 4) = o;
    }
}

// ---------------- persistent recurrence kernel ----------------------------
// Grid: 128 CTAs (jc = CTA id, 4 hidden cols), 256 threads.
// Matmul: thread = (col16 = tid&15 -> (g,dj), kq = tid>>4 -> 32-k slice).
// Lee:    thread = (lb = tid>>2, lj = tid&3); z-free oscillator recurrence:
//   z_n = w0 + dec*(u_n - v_n) for n>=1, so with hw = hx - 0.5*w0, dh = 0.5*dec:
//   su = hw + (0.6-dh)u + (0.6+dh)v ; sv = hw + (-0.6-dh)u + (-0.6+dh)v.
//   Iter 1 peeled (u1 = v1 = f(hx)); final z recovered once after the loop.
// SMEM: ws[512][16] weights (staged once) | hs[512][64] (linear copy) | red[128][66].
__global__ __launch_bounds__(NTHR, 1) void lstm_persist(
    const float* __restrict__ Wh,
    const float* __restrict__ h0,
    const float* __restrict__ c0,
    float* __restrict__ out,
    int write_state) {

    extern __shared__ float smem[];
    float* ws  = smem;                     // 8192 floats
    float* hs  = smem + 8192;              // 32768 floats
    float* red = smem + 8192 + 32768;      // 8448 floats (rows of 66)

    int tid = threadIdx.x;
    int col16 = tid & 15;
    int kq = tid >> 4;                     // 0..15
    int jc = blockIdx.x;
    int lane = tid & 31, wrp = tid >> 5;

    int lb = tid >> 2;                     // Lee: batch
    int lj = tid & 3;                      // Lee: hidden col within jc

    // ---- stage weights once: ws[k*16 + c] = Wh[k][g(c)*512 + jc*4 + dj(c)]
#pragma unroll 4
    for (int it = 0; it < 32; it++) {
        int idx = it * 256 + tid;
        int k = idx >> 4;
        int c = idx & 15;
        ws[idx] = Wh[(size_t)k * G4 + (c >> 2) * HID + jc * 4 + (c & 3)];
    }

    // ---- init transposed state + private cell register
    int hcol = jc * 4 + lj;
    int hidx = lb * HID + hcol;            // row-major index (for out/state)
    int tidx = hcol * BS + lb;             // transposed index
    g_h[0][tidx] = h0[hidx];
    float c_reg = c0[hidx];
    __syncthreads();

    const int kbase = kq * 32;

    for (int t = 0; t < SEQ; t++) {
        // prefetch pre-activation terms (latency hides under barrier wait)
        const float* prerow = g_pre + ((size_t)t * BS + lb) * G4 + hcol;
        float p0 = prerow[0];
        float p1 = prerow[HID];
        float p2 = prerow[2 * HID];
        float p3 = prerow[3 * HID];

        grid_barrier((unsigned)(t + 1));

        // ---- stage h: linear coalesced copy (g_h already [k][b])
        const float* hsrc = g_h[t & 1];
#pragma unroll 8
        for (int it = 0; it < 32; it++) {
            int idx = (it * 256 + tid) * 4;
            *(float4*)&hs[idx] = *(const float4*)(hsrc + idx);
        }
        __syncthreads();

        // ---- matmul: acc over 64 b (32 f32x2 pairs), my col, my k-slice
        unsigned long long acc[32];
#pragma unroll
        for (int i = 0; i < 32; i++) acc[i] = 0ull;

#pragma unroll 4
        for (int kk = 0; kk < 32; kk++) {
            int k = kbase + kk;
            float wv = ws[k * 16 + col16];
            unsigned long long wd;
            asm("mov.b64 %0, {%1, %1};" : "=l"(wd) : "r"(__float_as_uint(wv)));
            const ulonglong2* hp = (const ulonglong2*)&hs[k * 64];
#pragma unroll
            for (int q = 0; q < 16; q++) {
                ulonglong2 hv = hp[q];
                FMA2(acc[2 * q],     hv.x, wd);
                FMA2(acc[2 * q + 1], hv.y, wd);
            }
        }

        // ---- reduce across kq: shfl halves 16-way, smem for the 8 warps
#pragma unroll
        for (int q = 0; q < 32; q++) {
            unsigned long long o = __shfl_xor_sync(0xffffffffu, acc[q], 16);
            unsigned long long s;
            ADD2(s, acc[q], o);
            acc[q] = s;
        }
        if (lane < 16) {
            float* rr = &red[(wrp * 16 + lane) * 66];
#pragma unroll
            for (int q = 0; q < 32; q++)
                *(unsigned long long*)&rr[2 * q] = acc[q];
        }
        __syncthreads();

        // ---- gate sums for (lb, lj)
        float xx[4];
        xx[0] = p0; xx[1] = p1; xx[2] = p2; xx[3] = p3;
#pragma unroll
        for (int gg = 0; gg < 4; gg++) {
            float s = xx[gg];
#pragma unroll
            for (int wv = 0; wv < 8; wv++)
                s += red[(wv * 16 + gg * 4 + lj) * 66 + lb];
            xx[gg] = s;
        }

        // ---- 4-wide interleaved Lee oscillators (i,f,o sig; g tanh)
        // z-free recurrence; paired activations share one RCP.
        // hx clamped to +-22 so exp args stay < 88 (no inf -> no NaN).
        float u[4], v[4], dec[4], w0g[4], hw[4], au[4], av[4], bu[4], bv[4];
#pragma unroll
        for (int l = 0; l < 4; l++) {
            float xv = xx[l];
            w0g[l] = (l == 2) ? ftanh(xv) : fsig(xv);
            dec[l] = __expf(-50.0f * xv * xv);
            float hx = fminf(fmaxf(0.5f * xv, -22.0f), 22.0f);
            float e  = (l == 2) ? ftanh(hx) : fsig(hx);   // peeled iter 1
            u[l] = e; v[l] = e;
            hw[l] = fmaf(-0.5f, w0g[l], hx);
            float dh = 0.5f * dec[l];
            au[l] = 0.6f - dh;  av[l] = 0.6f + dh;
            bu[l] = -0.6f - dh; bv[l] = -0.6f + dh;
        }
#pragma unroll 1
        for (int it = 0; it < 24; it++) {
#pragma unroll
            for (int l = 0; l < 4; l++) {
                float su = fmaf(au[l], u[l], fmaf(av[l], v[l], hw[l]));
                float sv = fmaf(bu[l], u[l], fmaf(bv[l], v[l], hw[l]));
                float ea, eb;
                if (l == 2) { ea = __expf(-2.0f * su); eb = __expf(-2.0f * sv); }
                else        { ea = __expf(-su);        eb = __expf(-sv); }
                float d1 = 1.0f + ea;
                float d2 = 1.0f + eb;
                float R  = frcp(d1 * d2);
                if (l == 2) {
                    u[l] = fmaf(2.0f * d2, R, -1.0f);   // tanh(su)
                    v[l] = fmaf(2.0f * d1, R, -1.0f);   // tanh(sv)
                } else {
                    u[l] = d2 * R;                       // sig(su)
                    v[l] = d1 * R;                       // sig(sv)
                }
            }
        }
        float z[4];
#pragma unroll
        for (int l = 0; l < 4; l++)
            z[l] = fmaf(u[l] - v[l], dec[l], w0g[l]);

        // ---- cell update + lee_tanh(c1), same z-free form
        float c1 = fmaf(z[1], c_reg, z[0] * z[2]);
        float wc   = ftanh(c1);
        float decc = __expf(-50.0f * c1 * c1);
        float hxc  = fminf(fmaxf(0.5f * c1, -22.0f), 22.0f);
        float ec   = ftanh(hxc);                         // peeled iter 1
        float uu = ec, vv = ec;
        float hwc = fmaf(-0.5f, wc, hxc);
        float dhc = 0.5f * decc;
        float auc = 0.6f - dhc,  avc = 0.6f + dhc;
        float buc = -0.6f - dhc, bvc = -0.6f + dhc;
#pragma unroll 1
        for (int it = 0; it < 24; it++) {
            float su = fmaf(auc, uu, fmaf(avc, vv, hwc));
            float sv = fmaf(buc, uu, fmaf(bvc, vv, hwc));
            float ea = __expf(-2.0f * su);
            float eb = __expf(-2.0f * sv);
            float d1 = 1.0f + ea;
            float d2 = 1.0f + eb;
            float R  = frcp(d1 * d2);
            uu = fmaf(2.0f * d2, R, -1.0f);
            vv = fmaf(2.0f * d1, R, -1.0f);
        }
        float zz = fmaf(uu - vv, decc, wc);

        float h1 = z[3] * zz;
        c_reg = c1;
        g_h[(t + 1) & 1][tidx] = h1;
        out[(size_t)lb * (SEQ * HID) + (size_t)t * HID + hcol] = h1;

        if (write_state && t == SEQ - 1) {
            out[(size_t)BS * SEQ * HID + hidx]            = h1;
            out[(size_t)BS * SEQ * HID + BS * HID + hidx] = c1;
        }
    }
}

// ---------------- launch -------------------------------------------------
extern "C" void kernel_launch(void* const* d_in, const int* in_sizes, int n_in,
                              void* d_out, int out_size) {
    const float* x    = (const float*)d_in[0];
    const float* Wi   = (const float*)d_in[1];
    const float* Wh   = (const float*)d_in[2];
    const float* bias = (const float*)d_in[3];
    const float* h0   = (const float*)d_in[4];
    const float* c0   = (const float*)d_in[5];
    float* out = (float*)d_out;

    const int SMEM_BYTES = (8192 + 32768 + 8448) * 4;   // 197632 B
    cudaFuncSetAttribute(lstm_persist,
                         cudaFuncAttributeMaxDynamicSharedMemorySize, SMEM_BYTES);

    dim3 gg(32, 512);
    gemm_pre<<<gg, 256>>>(x, Wi, bias);   // also resets barrier counters

    int ws = (out_size >= (int)((size_t)BS * SEQ * HID + 2 * BS * HID)) ? 1 : 0;
    lstm_persist<<<NCTA, NTHR, SMEM_BYTES>>>(Wh, h0, c0, out, ws);
}